// round 6
// baseline (speedup 1.0000x reference)
#include <cuda_runtime.h>
#include <math.h>

#define Bsz 128
#define Ssz 1024
#define Hsz 768
#define MAXV 25
#define NTOK 50                 // 2*MAXV
#define S_LEVI (Ssz - NTOK)     // 974

// Scratch for pooled activations (allocation-free rule: device global)
__device__ float g_pooled[Bsz * Hsz];

__device__ __forceinline__ float warp_sum(float v) {
#pragma unroll
    for (int o = 16; o > 0; o >>= 1) v += __shfl_xor_sync(0xffffffffu, v, o);
    return v;
}

// ---------------------------------------------------------------------------
// Kernel 1: per-batch masked attention pooling over the 50-token tail slice.
// One block per batch, 256 threads. Slice staged in dynamic smem (150 KB).
// ---------------------------------------------------------------------------
__global__ __launch_bounds__(256, 1)
void pool_kernel(const float* __restrict__ hidden,
                 const int*   __restrict__ verb32,   // int32 view; dtype detected
                 const float* __restrict__ subject,
                 const float* __restrict__ align_w,  // [2H]
                 const float* __restrict__ align_b,  // [1]
                 float*       __restrict__ pooled)   // [B,H]
{
    extern __shared__ float sh_tile[];   // NTOK * Hsz floats
    __shared__ float s_scores[NTOK];
    __shared__ float s_weights[NTOK];
    __shared__ float s_red[8];
    __shared__ float s_c;
    __shared__ int   s_v;

    const int b    = blockIdx.x;
    const int tid  = threadIdx.x;
    const int warp = tid >> 5;
    const int lane = tid & 31;

    // --- detect verb_count dtype (int64 vs int32) and load v for this batch ---
    if (tid == 0) {
        bool is64 = true;
        for (int i = 1; i < 2 * Bsz; i += 2) {
            if (verb32[i] != 0) { is64 = false; break; }
        }
        s_v = is64 ? verb32[2 * b] : verb32[b];
    }

    // --- stage contiguous slice hidden[b, 974:1024, :] into smem (float4) ---
    const float4* src = (const float4*)(hidden + ((size_t)b * Ssz + S_LEVI) * Hsz);
    float4* dst = (float4*)sh_tile;
#pragma unroll 4
    for (int i = tid; i < NTOK * Hsz / 4; i += 256) dst[i] = src[i];

    // --- subject score: c = dot(subject[b], align_w[0:H]) + bias ---
    float part = 0.f;
    for (int i = tid; i < Hsz; i += 256)
        part = fmaf(subject[b * Hsz + i], align_w[i], part);
    part = warp_sum(part);
    if (lane == 0) s_red[warp] = part;
    __syncthreads();   // also fences the smem tile copy + s_v
    if (tid == 0) {
        float c = 0.f;
#pragma unroll
        for (int i = 0; i < 8; i++) c += s_red[i];
        s_c = c + align_b[0];
    }
    __syncthreads();

    const int v = s_v;
    const float cb = s_c;
    const float* __restrict__ w2 = align_w + Hsz;

    // --- per-token scores: warp per token (8 warps over 50 tokens) ---
    for (int t = warp; t < NTOK; t += 8) {
        const float* row = sh_tile + t * Hsz;
        float s = 0.f;
        for (int i = lane; i < Hsz; i += 32) s = fmaf(row[i], w2[i], s);
        s = warp_sum(s);
        if (lane == 0) {
            bool active = (t < v) || (t >= MAXV && t < MAXV + v);
            s_scores[t] = active ? (s + cb) : -INFINITY;
        }
    }
    __syncthreads();

    // --- masked softmax over 50 scores (warp 0) ---
    if (warp == 0) {
        float a  = (lane < NTOK)      ? s_scores[lane]      : -INFINITY;
        float b2 = (lane + 32 < NTOK) ? s_scores[lane + 32] : -INFINITY;
        float m = fmaxf(a, b2);
#pragma unroll
        for (int o = 16; o > 0; o >>= 1)
            m = fmaxf(m, __shfl_xor_sync(0xffffffffu, m, o));
        if (!isfinite(m)) m = 0.f;
        float e1 = (a  > -INFINITY) ? expf(a  - m) : 0.f;
        float e2 = (b2 > -INFINITY) ? expf(b2 - m) : 0.f;
        float denom = warp_sum(e1 + e2);
        float inv = (denom > 0.f) ? (1.f / fmaxf(denom, 1e-30f)) : 0.f;
        if (lane < NTOK)      s_weights[lane]      = e1 * inv;
        if (lane + 32 < NTOK) s_weights[lane + 32] = e2 * inv;
    }
    __syncthreads();

    // --- pooled[h] = sum_t w[t] * slice[t,h] ---
    for (int h = tid; h < Hsz; h += 256) {
        float acc = 0.f;
#pragma unroll
        for (int t = 0; t < NTOK; t++)
            acc = fmaf(s_weights[t], sh_tile[t * Hsz + h], acc);
        pooled[b * Hsz + h] = acc;
    }
}

// ---------------------------------------------------------------------------
// Kernel 2: out[b,h] = tanh( sum_k pooled[b,k] * out_w[h,k] + out_b[h] )
// Tiles: TB=16 batches x TH=64 outputs per block, TK=32 k-chunk.
// grid = (H/TH=12, B/TB=8), 256 threads, 2x2 register blocking per thread.
// ---------------------------------------------------------------------------
#define TB 16
#define TH 64
#define TK 32

__global__ __launch_bounds__(256)
void gemm_tanh(const float* __restrict__ P,     // [B,H] pooled
               const float* __restrict__ W,     // [H,H] out_w (row-major, k contiguous)
               const float* __restrict__ bias,  // [H]
               float*       __restrict__ out)   // [B,H]
{
    __shared__ float sP[TB][TK];       // 2 KB
    __shared__ float sW[TK][TH + 1];   // 8.3 KB, padded (conflict-free transpose)

    const int tid = threadIdx.x;
    const int h0 = blockIdx.x * TH;
    const int b0 = blockIdx.y * TB;
    const int bg = tid >> 5;   // 0..7  -> batches {bg, bg+8}
    const int hg = tid & 31;   // 0..31 -> outputs {hg, hg+32}

    float a00 = 0.f, a01 = 0.f, a10 = 0.f, a11 = 0.f;

    for (int k0 = 0; k0 < Hsz; k0 += TK) {
        // load P tile: 16x32 = 512 floats, 2 per thread
        {
            int r = tid >> 5, c = tid & 31;
            sP[r][c]     = P[(b0 + r)     * Hsz + k0 + c];
            sP[r + 8][c] = P[(b0 + r + 8) * Hsz + k0 + c];
        }
        // load W tile transposed: 64 rows x 32 k -> sW[k][j]; float4 along k
        for (int q = tid; q < (TH * TK / 4); q += 256) {
            int j  = q >> 3;       // 0..63
            int kq = q & 7;        // 0..7
            float4 wv = *(const float4*)&W[(size_t)(h0 + j) * Hsz + k0 + kq * 4];
            sW[kq * 4 + 0][j] = wv.x;
            sW[kq * 4 + 1][j] = wv.y;
            sW[kq * 4 + 2][j] = wv.z;
            sW[kq * 4 + 3][j] = wv.w;
        }
        __syncthreads();

#pragma unroll
        for (int k = 0; k < TK; k++) {
            float p0 = sP[bg][k];
            float p1 = sP[bg + 8][k];
            float w0 = sW[k][hg];
            float w1 = sW[k][hg + 32];
            a00 = fmaf(p0, w0, a00);
            a01 = fmaf(p0, w1, a01);
            a10 = fmaf(p1, w0, a10);
            a11 = fmaf(p1, w1, a11);
        }
        __syncthreads();
    }

    const float bia0 = bias[h0 + hg];
    const float bia1 = bias[h0 + hg + 32];
    out[(size_t)(b0 + bg)     * Hsz + h0 + hg]      = tanhf(a00 + bia0);
    out[(size_t)(b0 + bg)     * Hsz + h0 + hg + 32] = tanhf(a01 + bia1);
    out[(size_t)(b0 + bg + 8) * Hsz + h0 + hg]      = tanhf(a10 + bia0);
    out[(size_t)(b0 + bg + 8) * Hsz + h0 + hg + 32] = tanhf(a11 + bia1);
}

// ---------------------------------------------------------------------------
extern "C" void kernel_launch(void* const* d_in, const int* in_sizes, int n_in,
                              void* d_out, int out_size)
{
    const float* hidden   = (const float*)d_in[0];
    const int*   verb32   = (const int*)  d_in[1];  // int32 view; dtype auto-detected
    const float* subject  = (const float*)d_in[2];
    const float* align_w  = (const float*)d_in[3];
    const float* align_b  = (const float*)d_in[4];
    const float* out_w    = (const float*)d_in[5];
    const float* out_b    = (const float*)d_in[6];
    float* out = (float*)d_out;

    float* pooled = nullptr;
    cudaGetSymbolAddress((void**)&pooled, g_pooled);

    const int smem_bytes = NTOK * Hsz * sizeof(float);  // 153600
    cudaFuncSetAttribute(pool_kernel,
                         cudaFuncAttributeMaxDynamicSharedMemorySize, smem_bytes);

    pool_kernel<<<Bsz, 256, smem_bytes>>>(hidden, verb32, subject,
                                          align_w, align_b, pooled);
    gemm_tanh<<<dim3(Hsz / TH, Bsz / TB), 256>>>(pooled, out_w, out_b, out);
}

// round 7
// speedup vs baseline: 1.9908x; 1.9908x over previous
#include <cuda_runtime.h>
#include <math.h>

#define Bsz 128
#define Ssz 1024
#define Hsz 768
#define MAXV 25
#define NTOK 50                 // 2*MAXV
#define S_LEVI (Ssz - NTOK)     // 974

// ---- GEMM split-K config ----
#define KSPLIT 8                // 768 / 8 = 96 k per split
#define GTB 32                  // batches per block
#define GTH 128                 // h-outputs per block
#define GTK 32                  // k per smem tile
#define NITER 3                 // 96 / 32
#define WPAD 4                  // sW row pad (keeps 16B alignment, breaks conflicts)

// Scratch (allocation-free rule: device globals)
__device__ float g_pooled[Bsz * Hsz];
__device__ float g_part[KSPLIT * Bsz * Hsz];   // 3.1 MB partial sums

__device__ __forceinline__ float warp_sum(float v) {
#pragma unroll
    for (int o = 16; o > 0; o >>= 1) v += __shfl_xor_sync(0xffffffffu, v, o);
    return v;
}

// ---------------------------------------------------------------------------
// Kernel 1: per-batch masked attention pooling over the 50-token tail slice.
// One block per batch, 512 threads. Slice staged in dynamic smem (150 KB).
// NOTE: the subject-hidden score term is a per-batch constant over all active
// tokens; it cancels exactly in softmax (s+c)-(m+c) = s-m, so it is skipped.
// ---------------------------------------------------------------------------
__global__ __launch_bounds__(512, 1)
void pool_kernel(const float* __restrict__ hidden,
                 const int*   __restrict__ verb32,   // int32 view; dtype detected
                 const float* __restrict__ align_w,  // [2H]
                 float*       __restrict__ pooled)   // [B,H]
{
    extern __shared__ float sh_tile[];   // NTOK * Hsz floats
    __shared__ float s_scores[NTOK];
    __shared__ float s_weights[NTOK];
    __shared__ int   s_v;

    const int b    = blockIdx.x;
    const int tid  = threadIdx.x;
    const int warp = tid >> 5;
    const int lane = tid & 31;

    // --- dtype detect (int64 vs int32) via 64 odd-word samples, warp 0 ---
    if (warp == 0) {
        int a = verb32[2 * lane + 1];
        int c = verb32[2 * lane + 65];
        unsigned nz = __ballot_sync(0xffffffffu, (a | c) != 0);
        if (lane == 0) s_v = nz ? verb32[b] : verb32[2 * b];
    }

    // --- stage contiguous slice hidden[b, 974:1024, :] into smem (float4) ---
    const float4* src = (const float4*)(hidden + ((size_t)b * Ssz + S_LEVI) * Hsz);
    float4* dst = (float4*)sh_tile;
#pragma unroll 4
    for (int i = tid; i < NTOK * Hsz / 4; i += 512) dst[i] = src[i];
    __syncthreads();

    const int v = s_v;
    const float* __restrict__ w2 = align_w + Hsz;

    // --- per-token scores: warp per token (16 warps over 50 tokens) ---
    for (int t = warp; t < NTOK; t += 16) {
        const float* row = sh_tile + t * Hsz;
        float s = 0.f;
#pragma unroll 6
        for (int i = lane; i < Hsz; i += 32) s = fmaf(row[i], w2[i], s);
        s = warp_sum(s);
        if (lane == 0) {
            bool active = (t < v) || (t >= MAXV && t < MAXV + v);
            s_scores[t] = active ? s : -INFINITY;
        }
    }
    __syncthreads();

    // --- masked softmax over 50 scores (warp 0) ---
    if (warp == 0) {
        float a  = (lane < NTOK)      ? s_scores[lane]      : -INFINITY;
        float b2 = (lane + 32 < NTOK) ? s_scores[lane + 32] : -INFINITY;
        float m = fmaxf(a, b2);
#pragma unroll
        for (int o = 16; o > 0; o >>= 1)
            m = fmaxf(m, __shfl_xor_sync(0xffffffffu, m, o));
        if (!isfinite(m)) m = 0.f;
        float e1 = (a  > -INFINITY) ? expf(a  - m) : 0.f;
        float e2 = (b2 > -INFINITY) ? expf(b2 - m) : 0.f;
        float denom = warp_sum(e1 + e2);
        float inv = (denom > 0.f) ? (1.f / fmaxf(denom, 1e-30f)) : 0.f;
        if (lane < NTOK)      s_weights[lane]      = e1 * inv;
        if (lane + 32 < NTOK) s_weights[lane + 32] = e2 * inv;
    }
    __syncthreads();

    // --- pooled[h] = sum_t w[t] * slice[t,h] ---
    for (int h = tid; h < Hsz; h += 512) {
        float acc = 0.f;
#pragma unroll
        for (int t = 0; t < NTOK; t++)
            acc = fmaf(s_weights[t], sh_tile[t * Hsz + h], acc);
        pooled[b * Hsz + h] = acc;
    }
}

// ---------------------------------------------------------------------------
// Kernel 2: split-K partial GEMM. part[z][b][h] = sum_{k in split z} P[b,k]*W[h,k]
// grid = (6 h-tiles, 4 b-tiles, 8 k-splits) = 192 blocks, 256 threads.
// Per thread: 4b x 4h register tile. Double-buffered smem, register prefetch.
// ---------------------------------------------------------------------------
__global__ __launch_bounds__(256, 1)
void gemm_partial(const float* __restrict__ P,     // [B,H] pooled
                  const float* __restrict__ W,     // [H,H] out_w (k contiguous)
                  float*       __restrict__ part)  // [KSPLIT,B,H]
{
    __shared__ float sP[2][GTB][GTK];          // 8 KB
    __shared__ float sW[2][GTK][GTH + WPAD];   // 33.8 KB (k-major, padded)

    const int tid  = threadIdx.x;
    const int wid  = tid >> 5;          // 0..7  -> 4 batches each
    const int lane = tid & 31;          // 0..31 -> 4 h each (float4)
    const int h0   = blockIdx.x * GTH;
    const int b0   = blockIdx.y * GTB;
    const int ks0  = blockIdx.z * (Hsz / KSPLIT);   // 96-wide k range

    // tile-load index precompute
    const int pr  = tid >> 3;           // 0..31  P row
    const int pc4 = tid & 7;            // 0..7   P float4 col

    float4 pre_p;
    float4 pre_w[4];

    // prefetch tile 0
    {
        const int kk = ks0;
        pre_p = *(const float4*)&P[(size_t)(b0 + pr) * Hsz + kk + pc4 * 4];
#pragma unroll
        for (int i = 0; i < 4; i++) {
            int q  = tid + i * 256;
            int hh = q >> 3, c4 = q & 7;
            pre_w[i] = *(const float4*)&W[(size_t)(h0 + hh) * Hsz + kk + c4 * 4];
        }
    }
    // store tile 0 -> buf 0
    {
        *(float4*)&sP[0][pr][pc4 * 4] = pre_p;
#pragma unroll
        for (int i = 0; i < 4; i++) {
            int q  = tid + i * 256;
            int hh = q >> 3, c4 = q & 7;
            sW[0][c4 * 4 + 0][hh] = pre_w[i].x;
            sW[0][c4 * 4 + 1][hh] = pre_w[i].y;
            sW[0][c4 * 4 + 2][hh] = pre_w[i].z;
            sW[0][c4 * 4 + 3][hh] = pre_w[i].w;
        }
    }
    __syncthreads();

    float4 acc[4];
#pragma unroll
    for (int j = 0; j < 4; j++) acc[j] = make_float4(0.f, 0.f, 0.f, 0.f);

#pragma unroll
    for (int it = 0; it < NITER; it++) {
        const int cur = it & 1;

        // prefetch next tile into registers (hidden under compute)
        if (it < NITER - 1) {
            const int kk = ks0 + (it + 1) * GTK;
            pre_p = *(const float4*)&P[(size_t)(b0 + pr) * Hsz + kk + pc4 * 4];
#pragma unroll
            for (int i = 0; i < 4; i++) {
                int q  = tid + i * 256;
                int hh = q >> 3, c4 = q & 7;
                pre_w[i] = *(const float4*)&W[(size_t)(h0 + hh) * Hsz + kk + c4 * 4];
            }
        }

        // compute current tile: 32 k-steps, 16 FMA each
#pragma unroll
        for (int k = 0; k < GTK; k++) {
            float4 wv = *(const float4*)&sW[cur][k][lane * 4];
            float p0 = sP[cur][wid * 4 + 0][k];
            float p1 = sP[cur][wid * 4 + 1][k];
            float p2 = sP[cur][wid * 4 + 2][k];
            float p3 = sP[cur][wid * 4 + 3][k];
            acc[0].x = fmaf(p0, wv.x, acc[0].x); acc[0].y = fmaf(p0, wv.y, acc[0].y);
            acc[0].z = fmaf(p0, wv.z, acc[0].z); acc[0].w = fmaf(p0, wv.w, acc[0].w);
            acc[1].x = fmaf(p1, wv.x, acc[1].x); acc[1].y = fmaf(p1, wv.y, acc[1].y);
            acc[1].z = fmaf(p1, wv.z, acc[1].z); acc[1].w = fmaf(p1, wv.w, acc[1].w);
            acc[2].x = fmaf(p2, wv.x, acc[2].x); acc[2].y = fmaf(p2, wv.y, acc[2].y);
            acc[2].z = fmaf(p2, wv.z, acc[2].z); acc[2].w = fmaf(p2, wv.w, acc[2].w);
            acc[3].x = fmaf(p3, wv.x, acc[3].x); acc[3].y = fmaf(p3, wv.y, acc[3].y);
            acc[3].z = fmaf(p3, wv.z, acc[3].z); acc[3].w = fmaf(p3, wv.w, acc[3].w);
        }

        if (it < NITER - 1) {
            __syncthreads();   // everyone done reading buf cur
            const int nxt = cur ^ 1;
            *(float4*)&sP[nxt][pr][pc4 * 4] = pre_p;
#pragma unroll
            for (int i = 0; i < 4; i++) {
                int q  = tid + i * 256;
                int hh = q >> 3, c4 = q & 7;
                sW[nxt][c4 * 4 + 0][hh] = pre_w[i].x;
                sW[nxt][c4 * 4 + 1][hh] = pre_w[i].y;
                sW[nxt][c4 * 4 + 2][hh] = pre_w[i].z;
                sW[nxt][c4 * 4 + 3][hh] = pre_w[i].w;
            }
            __syncthreads();   // next buf ready
        }
    }

    // store partials: coalesced float4 per (b,h0+4*lane)
    float* base = part + ((size_t)blockIdx.z * Bsz) * Hsz;
#pragma unroll
    for (int j = 0; j < 4; j++) {
        *(float4*)&base[(size_t)(b0 + wid * 4 + j) * Hsz + h0 + lane * 4] = acc[j];
    }
}

// ---------------------------------------------------------------------------
// Kernel 3: epilogue. out[b,h] = tanh( sum_z part[z][b][h] + bias[h] )
// 96 blocks x 256 threads, one float4 per thread.
// ---------------------------------------------------------------------------
__global__ __launch_bounds__(256)
void epilogue(const float* __restrict__ part,
              const float* __restrict__ bias,
              float*       __restrict__ out)
{
    const int idx = blockIdx.x * 256 + threadIdx.x;   // 0..24575 float4 slots
    const float4* p4 = (const float4*)part;
    const int b  = idx / (Hsz / 4);
    const int h4 = idx % (Hsz / 4);

    float4 s = make_float4(0.f, 0.f, 0.f, 0.f);
#pragma unroll
    for (int z = 0; z < KSPLIT; z++) {
        float4 v = p4[(size_t)(z * Bsz + b) * (Hsz / 4) + h4];
        s.x += v.x; s.y += v.y; s.z += v.z; s.w += v.w;
    }
    float4 bi = ((const float4*)bias)[h4];
    float4 o;
    o.x = tanhf(s.x + bi.x);
    o.y = tanhf(s.y + bi.y);
    o.z = tanhf(s.z + bi.z);
    o.w = tanhf(s.w + bi.w);
    ((float4*)out)[idx] = o;
}

// ---------------------------------------------------------------------------
extern "C" void kernel_launch(void* const* d_in, const int* in_sizes, int n_in,
                              void* d_out, int out_size)
{
    const float* hidden   = (const float*)d_in[0];
    const int*   verb32   = (const int*)  d_in[1];  // int32 view; dtype auto-detected
    const float* align_w  = (const float*)d_in[3];
    const float* out_w    = (const float*)d_in[5];
    const float* out_b    = (const float*)d_in[6];
    float* out = (float*)d_out;

    float* pooled = nullptr;
    float* part   = nullptr;
    cudaGetSymbolAddress((void**)&pooled, g_pooled);
    cudaGetSymbolAddress((void**)&part,   g_part);

    const int smem_bytes = NTOK * Hsz * sizeof(float);  // 153600
    cudaFuncSetAttribute(pool_kernel,
                         cudaFuncAttributeMaxDynamicSharedMemorySize, smem_bytes);

    pool_kernel<<<Bsz, 512, smem_bytes>>>(hidden, verb32, align_w, pooled);
    gemm_partial<<<dim3(Hsz / GTH, Bsz / GTB, KSPLIT), 256>>>(pooled, out_w, part);
    epilogue<<<(Bsz * Hsz / 4) / 256, 256>>>(part, out_b, out);
}